// round 14
// baseline (speedup 1.0000x reference)
#include <cuda_runtime.h>
#include <cstdint>

// C4ByteTransformer R14: zero-communication structure (R12) + f32x2 packed
// FMA convolution. ptxas never auto-emits FFMA2; we reach it via PTX
// fma.rn.f32x2. Operand pairs come pre-packed from SMEM:
//   EAdup[a] = (EA[a], EA[a]) as one 64-bit word (splat multiplier)
//   EBq[j]   = EBp[j+1]  (4-byte-shifted copy -> odd window pairs 8B-aligned)
// Accumulator packs (s0,s1),(s2,s3); same add order as scalar version.
// Carry chain runs per-thread in tid<256 (no final barrier, no serialization).

#define FMA2(acc, a, b) \
    asm("fma.rn.f32x2 %0, %1, %2, %0;" : "+l"(acc) : "l"(a), "l"(b))

__global__ __launch_bounds__(1024, 1)
void c4_f32x2_kernel(const float* __restrict__ a_emb,
                     const float* __restrict__ b_emb,
                     float* __restrict__ out) {
    __shared__ __align__(16) float EA_all[1024];   // [s][a], all 4 steps
    __shared__ __align__(16) float EB_all[1024];   // [s][b], all 4 steps
    __shared__ __align__(16) float EBp[1024];      // own-step EB at [255+b], 0-pad
    __shared__ __align__(16) float EBq[1024];      // EBq[j] = EBp[j+1]
    __shared__ __align__(16) unsigned long long EAdup[256];  // own-step splat EA
    __shared__ __align__(16) float Spart[8 * 512];
    __shared__ __align__(16) float S[513];         // S[0]=0, S[1+m]=S_step[m]
    __shared__ float chunkTot[32];                 // per-warp chunk sums of EB
    __shared__ float Trip[4][4];                   // [s]{Tlow, S255, SumA, SumB}

    const int tid  = threadIdx.x;
    const int step = blockIdx.x;
    const int lane = tid & 31;
    const int w    = tid >> 5;

    // ---- Phase A: all 4 steps' exponentials; thread=(s=tid>>8, e=tid&255) ----
    const float av = a_emb[tid];
    const float bv = b_emb[tid];
    float ebp = 0.f;                               // own-step padded EB
    if (tid >= 255 && tid < 511)
        ebp = __expf(10.f * b_emb[(step << 8) + tid - 255]);
    const float eav = __expf(10.f * av);
    const float ebv = __expf(10.f * bv);
    EA_all[tid] = eav;
    EB_all[tid] = ebv;
    EBp[tid]    = ebp;
    if (tid > 0) EBq[tid - 1] = ebp;               // shifted copy
    else         EBq[1023]    = 0.f;
    if ((tid >> 8) == step) {                      // own-step splat EA
        const unsigned int u = __float_as_uint(eav);
        EAdup[tid & 255] = ((unsigned long long)u << 32) | u;
    }
    if (tid < 16) ((float*)Trip)[tid] = 0.f;
    if (tid == 0) S[0] = 0.f;
    __syncthreads();                               // #1

    // ---- Phase B: convolution partials for OWN step, packed f32x2 ----
    // thread=(as,mg): outputs m in [4mg,4mg+3], a in [32as,32as+31].
    // w_i = EBp[J+i], J = J0-4k;  s_r += EA[a] * w[3-da+r].
    {
        const int as    = tid >> 7;
        const int mg    = tid & 127;
        const int m0    = mg << 2;
        const int abase = as << 5;
        const int J0    = 252 + m0 - abase;        // even, in [28, 760]
        unsigned long long acc01 = 0ull, acc23 = 0ull;   // (s0,s1),(s2,s3)
        #pragma unroll
        for (int k = 0; k < 8; ++k) {
            const int J  = J0 - 4 * k;
            const int ai = abase + 4 * k;
            const unsigned long long ea0 = EAdup[ai];
            const unsigned long long ea1 = EAdup[ai + 1];
            const unsigned long long ea2 = EAdup[ai + 2];
            const unsigned long long ea3 = EAdup[ai + 3];
            const unsigned long long PA = *(const unsigned long long*)&EBp[J];     // (w0,w1)
            const unsigned long long PB = *(const unsigned long long*)&EBp[J + 2]; // (w2,w3)
            const unsigned long long PC = *(const unsigned long long*)&EBp[J + 4]; // (w4,w5)
            const unsigned long long QA = *(const unsigned long long*)&EBq[J];     // (w1,w2)
            const unsigned long long QB = *(const unsigned long long*)&EBq[J + 2]; // (w3,w4)
            const unsigned long long QC = *(const unsigned long long*)&EBq[J + 4]; // (w5,w6)
            FMA2(acc01, ea0, QB);  FMA2(acc23, ea0, QC);   // da=0
            FMA2(acc01, ea1, PB);  FMA2(acc23, ea1, PC);   // da=1
            FMA2(acc01, ea2, QA);  FMA2(acc23, ea2, QB);   // da=2
            FMA2(acc01, ea3, PA);  FMA2(acc23, ea3, PB);   // da=3
        }
        unsigned int u0, u1, u2, u3;
        asm("mov.b64 {%0,%1}, %2;" : "=r"(u0), "=r"(u1) : "l"(acc01));
        asm("mov.b64 {%0,%1}, %2;" : "=r"(u2), "=r"(u3) : "l"(acc23));
        *(float4*)&Spart[as * 512 + m0] =
            make_float4(__uint_as_float(u0), __uint_as_float(u1),
                        __uint_as_float(u2), __uint_as_float(u3));
    }

    // ---- Phase S1: warp inclusive scan of EB (thread=(s,j)) ----
    float pb = ebv;
    #pragma unroll
    for (int off = 1; off < 32; off <<= 1) {
        float n = __shfl_up_sync(0xffffffffu, pb, off);
        if (lane >= off) pb += n;
    }
    if (lane == 31) chunkTot[w] = pb;
    __syncthreads();                               // #2 (covers Spart+chunkTot)

    // ---- Phase S2: finish prefix, triple contributions, reduce ----
    {
        const int c = w & 7, sbase = (w >> 3) << 3;
        float offsum = 0.f;
        for (int cc = 0; cc < c; ++cc) offsum += chunkTot[sbase + cc];
        pb += offsum;                              // pb = inclusive prefix PB[j]
    }
    {
        const int sj = tid >> 8, j = tid & 255;
        const float ea_rev = EA_all[(sj << 8) + 255 - j];
        float cl = ea_rev * pb;                    // -> Tlow
        float cs = ea_rev * ebv;                   // -> S255
        float ca = eav;                            // -> SumA
        float cb = ebv;                            // -> SumB
        #pragma unroll
        for (int off = 16; off > 0; off >>= 1) {
            cl += __shfl_down_sync(0xffffffffu, cl, off);
            cs += __shfl_down_sync(0xffffffffu, cs, off);
            ca += __shfl_down_sync(0xffffffffu, ca, off);
            cb += __shfl_down_sync(0xffffffffu, cb, off);
        }
        if (lane == 0) {
            atomicAdd(&Trip[sj][0], cl);
            atomicAdd(&Trip[sj][1], cs);
            atomicAdd(&Trip[sj][2], ca);
            atomicAdd(&Trip[sj][3], cb);
        }
    }

    // ---- Phase C: combine conv partials into S ----
    if (tid < 512) {
        float s = 0.f;
        #pragma unroll
        for (int p = 0; p < 8; ++p) s += Spart[p * 512 + tid];
        S[1 + tid] = s;                            // S[m=tid]; S[511]=0 naturally
    }
    __syncthreads();                               // #3 (covers Trip atomics + S)

    // ---- Phase F: per-thread carry chain + outputs (tid<256) ----
    if (tid < 256) {
        float E0s = 1.f, E1s = 1.f, iZs = 1.f;
        float c0 = 1.f, c1 = 0.f;                  // carry0 = (1, 0)
        #pragma unroll
        for (int s = 0; s < 4; ++s) {
            const float Tlow  = Trip[s][0];
            const float S255  = Trip[s][1];
            const float Tall  = Trip[s][2] * Trip[s][3];
            const float Thigh = Tall - Tlow;
            const float E0 = __expf(10.f * c0), E1 = __expf(10.f * c1);
            const float iZ = 1.0f / ((E0 + E1) * Tall);
            if (s == step) { E0s = E0; E1s = E1; iZs = iZ; }
            c0 = (E0 * Tlow  + E1 * (Tlow  - S255)) * iZ;
            c1 = (E0 * Thigh + E1 * (Thigh + S255)) * iZ;
        }
        // c=0: bins m=d and m=d+256 ; c=1: bins m=d-1 and m=d+255
        const float num = E0s * (S[1 + tid] + S[257 + tid])
                        + E1s * (S[tid]     + S[256 + tid]);
        out[(step << 8) + tid] = num * iZs;
    }
}

extern "C" void kernel_launch(void* const* d_in, const int* in_sizes, int n_in,
                              void* d_out, int out_size) {
    const float* a_emb = (const float*)d_in[0];   // [4, 256]
    const float* b_emb = (const float*)d_in[1];   // [4, 256]
    float* out = (float*)d_out;                   // [4, 256]
    (void)in_sizes; (void)n_in; (void)out_size;
    c4_f32x2_kernel<<<4, 1024>>>(a_emb, b_emb, out);
}

// round 15
// speedup vs baseline: 1.6442x; 1.6442x over previous
#include <cuda_runtime.h>

// C4ByteTransformer R15: circular-convolution formulation.
// Outputs need only Z[m] = S[m] + S[m+256] = circular conv of EA,EB
// (65536 MACs, half the padded linear conv):
//   num[d] = E0*Z[d] + E1*Z[(d-1)&255].
// Carry-chain triples {Tlow, S255, SumA, SumB} come from the O(256)
// prefix-scan closed forms (R12-validated). Zero inter-CTA communication;
// classic launch; conv keeps the 2xLDS.128-per-iteration structure (R14
// post-mortem: LDS instruction count is as binding as FFMA count).

__global__ __launch_bounds__(1024, 1)
void c4_circ_kernel(const float* __restrict__ a_emb,
                    const float* __restrict__ b_emb,
                    float* __restrict__ out) {
    __shared__ __align__(16) float EA_all[1024];   // [s][a], all 4 steps
    __shared__ __align__(16) float EBc2[512];      // own-step EB duplicated x2
    __shared__ __align__(16) float Spart[16 * 256];
    __shared__ __align__(16) float Z[256];         // circular conv result
    __shared__ float chunkTot[32];                 // per-warp chunk sums of EB
    __shared__ float Trip[4][4];                   // [s]{Tlow, S255, SumA, SumB}

    const int tid  = threadIdx.x;
    const int step = blockIdx.x;
    const int lane = tid & 31;
    const int w    = tid >> 5;                     // warp 0..31

    // ---- Phase A: all 4 steps' exponentials; thread=(s=tid>>8, e=tid&255) ----
    const float av  = a_emb[tid];
    const float bv  = b_emb[tid];
    const float eav = __expf(10.f * av);
    const float ebv = __expf(10.f * bv);
    EA_all[tid] = eav;
    if ((tid >> 8) == step) {                      // own-step EB, duplicated
        const int e = tid & 255;
        EBc2[e]       = ebv;
        EBc2[256 + e] = ebv;
    }
    if (tid < 16) ((float*)Trip)[tid] = 0.f;
    __syncthreads();                               // #1

    // ---- Phase B: circular conv partials for OWN step ----
    // thread=(as 0..15, mg 0..63): outputs m in [4mg,4mg+3], a in [16as,16as+15]
    // Z index j = 256 + m - a  ->  w[4 + r - da] with w[i] = EBc2[J0-4k+i].
    const float* EA = &EA_all[step << 8];
    {
        const int as    = tid >> 6;
        const int mg    = tid & 63;
        const int m0    = mg << 2;
        const int abase = as << 4;
        const int J0    = 252 + m0 - abase;        // in [12, 504], 16B aligned
        float4 lo = *(const float4*)&EBc2[J0];
        float4 hi = *(const float4*)&EBc2[J0 + 4];
        float s0 = 0.f, s1 = 0.f, s2 = 0.f, s3 = 0.f;
        #pragma unroll
        for (int k = 0; k < 4; ++k) {
            float4 ea = *(const float4*)&EA[abase + 4 * k];
            s0 = fmaf(ea.x, hi.x, s0); s1 = fmaf(ea.x, hi.y, s1);
            s2 = fmaf(ea.x, hi.z, s2); s3 = fmaf(ea.x, hi.w, s3);
            s0 = fmaf(ea.y, lo.w, s0); s1 = fmaf(ea.y, hi.x, s1);
            s2 = fmaf(ea.y, hi.y, s2); s3 = fmaf(ea.y, hi.z, s3);
            s0 = fmaf(ea.z, lo.z, s0); s1 = fmaf(ea.z, lo.w, s1);
            s2 = fmaf(ea.z, hi.x, s2); s3 = fmaf(ea.z, hi.y, s3);
            s0 = fmaf(ea.w, lo.y, s0); s1 = fmaf(ea.w, lo.z, s1);
            s2 = fmaf(ea.w, lo.w, s2); s3 = fmaf(ea.w, hi.x, s3);
            if (k < 3) {                           // slide window down by 4
                hi = lo;
                lo = *(const float4*)&EBc2[J0 - 4 * (k + 1)];
            }
        }
        *(float4*)&Spart[as * 256 + m0] = make_float4(s0, s1, s2, s3);
    }

    // ---- Phase S1: warp inclusive scan of EB (thread=(s,j)) ----
    float pb = ebv;
    #pragma unroll
    for (int off = 1; off < 32; off <<= 1) {
        float n = __shfl_up_sync(0xffffffffu, pb, off);
        if (lane >= off) pb += n;
    }
    if (lane == 31) chunkTot[w] = pb;
    __syncthreads();                               // #2 (covers Spart+chunkTot)

    // ---- Phase S2: finish prefix, triple contributions, reduce ----
    {
        const int c = w & 7, sbase = (w >> 3) << 3;
        float offsum = 0.f;
        for (int cc = 0; cc < c; ++cc) offsum += chunkTot[sbase + cc];
        pb += offsum;                              // inclusive prefix PB[j]
    }
    {
        const int sj = tid >> 8, j = tid & 255;
        const float ea_rev = EA_all[(sj << 8) + 255 - j];
        float cl = ea_rev * pb;                    // -> Tlow
        float cs = ea_rev * ebv;                   // -> S255
        float ca = eav;                            // -> SumA
        float cb = ebv;                            // -> SumB
        #pragma unroll
        for (int off = 16; off > 0; off >>= 1) {
            cl += __shfl_down_sync(0xffffffffu, cl, off);
            cs += __shfl_down_sync(0xffffffffu, cs, off);
            ca += __shfl_down_sync(0xffffffffu, ca, off);
            cb += __shfl_down_sync(0xffffffffu, cb, off);
        }
        if (lane == 0) {
            atomicAdd(&Trip[sj][0], cl);
            atomicAdd(&Trip[sj][1], cs);
            atomicAdd(&Trip[sj][2], ca);
            atomicAdd(&Trip[sj][3], cb);
        }
    }

    // ---- Phase C: combine conv partials into Z ----
    if (tid < 256) {
        float s = 0.f;
        #pragma unroll
        for (int p = 0; p < 16; ++p) s += Spart[p * 256 + tid];
        Z[tid] = s;
    }
    __syncthreads();                               // #3 (covers Trip + Z)

    // ---- Phase F: per-thread carry chain + outputs (tid<256) ----
    if (tid < 256) {
        float E0s = 1.f, E1s = 1.f, iZs = 1.f;
        float c0 = 1.f, c1 = 0.f;                  // carry0 = (1, 0)
        #pragma unroll
        for (int s = 0; s < 4; ++s) {
            const float Tlow  = Trip[s][0];
            const float S255  = Trip[s][1];
            const float Tall  = Trip[s][2] * Trip[s][3];
            const float Thigh = Tall - Tlow;
            const float E0 = __expf(10.f * c0), E1 = __expf(10.f * c1);
            const float iZ = 1.0f / ((E0 + E1) * Tall);
            if (s == step) { E0s = E0; E1s = E1; iZs = iZ; }
            c0 = (E0 * Tlow  + E1 * (Tlow  - S255)) * iZ;
            c1 = (E0 * Thigh + E1 * (Thigh + S255)) * iZ;
        }
        const float num = E0s * Z[tid] + E1s * Z[(tid + 255) & 255];
        out[(step << 8) + tid] = num * iZs;
    }
}

extern "C" void kernel_launch(void* const* d_in, const int* in_sizes, int n_in,
                              void* d_out, int out_size) {
    const float* a_emb = (const float*)d_in[0];   // [4, 256]
    const float* b_emb = (const float*)d_in[1];   // [4, 256]
    float* out = (float*)d_out;                   // [4, 256]
    (void)in_sizes; (void)n_in; (void)out_size;
    c4_circ_kernel<<<4, 1024>>>(a_emb, b_emb, out);
}